// round 1
// baseline (speedup 1.0000x reference)
#include <cuda_runtime.h>
#include <math.h>

#define C 128
#define NE_MAX 800000
#define NN_MAX 50000
#define BN_EPS 1e-5f

typedef unsigned long long u64;

// ---------------- scratch (device globals; no runtime alloc allowed) ----------------
__device__ float g_h[(size_t)NE_MAX * C];     // edge MLP pre-BN output (409.6 MB)
__device__ float g_xa[(size_t)NN_MAX * C];    // x @ w1a^T
__device__ float g_agg[(size_t)NN_MAX * C];   // scatter sum
__device__ float g_pre[(size_t)NN_MAX * C];   // node MLP pre-BN output
__device__ float g_w1at[C * C];               // [k][j] = w1[j][k]
__device__ float g_w1bt[C * C];               // [k][j] = w1[j][k+C]
__device__ float g_w2t[2 * C * C];            // [k][j] = w2[j][k]
__device__ float g_cnt[NN_MAX];
__device__ float g_inv[NN_MAX];
__device__ float g_s1[C], g_q1[C], g_s2[C], g_q2[C];
__device__ float g_a1[C], g_c1[C], g_a2[C], g_c2[C];

// ---------------- f32x2 packed math helpers ----------------
__device__ __forceinline__ u64 dupf(float v) {
    u64 d; asm("mov.b64 %0, {%1, %1};" : "=l"(d) : "f"(v)); return d;
}
__device__ __forceinline__ void ffma2(u64& d, u64 a, u64 b) {
    asm("fma.rn.f32x2 %0, %1, %2, %0;" : "+l"(d) : "l"(a), "l"(b));
}
__device__ __forceinline__ float f2lo(u64 v) { return __uint_as_float((unsigned)v); }
__device__ __forceinline__ float f2hi(u64 v) { return __uint_as_float((unsigned)(v >> 32)); }

__device__ __forceinline__ float eluf(float v) { return v > 0.f ? v : expm1f(v); }

// ---------------- misc small kernels ----------------
__global__ void zero_kernel() {
    int g = blockIdx.x * 256 + threadIdx.x;
    if (g < NN_MAX * C / 4) ((float4*)g_agg)[g] = make_float4(0.f, 0.f, 0.f, 0.f);
    if (g < NN_MAX) g_cnt[g] = 0.f;
    if (g < C) { g_s1[g] = 0.f; g_q1[g] = 0.f; g_s2[g] = 0.f; g_q2[g] = 0.f; }
}

__global__ void prep_w(const float* __restrict__ w1, const float* __restrict__ w2) {
    int k = blockIdx.x;     // 0..255
    int j = threadIdx.x;    // 0..127
    if (k < C) {
        g_w1at[k * C + j] = w1[j * 2 * C + k];
        g_w1bt[k * C + j] = w1[j * 2 * C + C + k];
    }
    g_w2t[k * C + j] = w2[j * 2 * C + k];
}

__global__ void count_kernel(const int* __restrict__ col, int E) {
    int e = blockIdx.x * 256 + threadIdx.x;
    if (e < E) atomicAdd(&g_cnt[col[e]], 1.f);
}

__global__ void inv_kernel(int n) {
    int i = blockIdx.x * 256 + threadIdx.x;
    if (i < n) g_inv[i] = 1.f / fmaxf(g_cnt[i], 1.f);
}

// ---------------- GEMM: out[m][j] = sum_k A[m][k] * Bt[k][j] (+ epilogue) ----------------
// MODE 0: A=x (M x 128), Bt=g_w1at, Out=g_xa, no bias
// MODE 1: A=edge_attr (M x 128), Bt=g_w1bt, Out=g_h, epilogue += g_xa[row[m]] + b1
// MODE 2: A=concat(x, g_agg*g_inv) (M x 256), Bt=g_w2t, Out=g_pre, epilogue += b2
template <int MODE, int KD>
__global__ void __launch_bounds__(256) gemm_kernel(
    const float* __restrict__ A, const float* __restrict__ bias,
    const int* __restrict__ rowidx, int M)
{
    constexpr int BM = 128, BK = 32, AS = 132;
    __shared__ __align__(16) float Asm[BK][AS];   // transposed: [k][m]
    __shared__ __align__(16) float Bsm[BK][C];

    const float* Bt = (MODE == 0) ? g_w1at : (MODE == 1) ? g_w1bt : g_w2t;
    float* Out = (MODE == 0) ? g_xa : (MODE == 1) ? g_h : g_pre;

    int tid = threadIdx.x;
    int tx = tid & 15, ty = tid >> 4;
    int m0 = tx * 8, n0 = ty * 8;
    int mbase = blockIdx.x * BM;

    u64 acc[4][8];
#pragma unroll
    for (int i = 0; i < 4; i++)
#pragma unroll
        for (int j = 0; j < 8; j++) acc[i][j] = 0ull;

    for (int k0 = 0; k0 < KD; k0 += BK) {
        if (k0) __syncthreads();
        // stage A (transposed into smem)
#pragma unroll
        for (int i = 0; i < 4; i++) {
            int idx = tid + i * 256;         // 0..1023
            int ml = idx >> 3;               // 0..127
            int kq = idx & 7;                // float4 slot within BK=32
            int m = mbase + ml; if (m >= M) m = M - 1;
            int k = k0 + kq * 4;
            float4 v;
            if (MODE == 2) {
                if (k < C) {
                    v = *(const float4*)(A + (size_t)m * C + k);
                } else {
                    v = *(const float4*)(g_agg + (size_t)m * C + (k - C));
                    float s = g_inv[m];
                    v.x *= s; v.y *= s; v.z *= s; v.w *= s;
                }
            } else {
                v = *(const float4*)(A + (size_t)m * KD + k);
            }
            Asm[kq * 4 + 0][ml] = v.x;
            Asm[kq * 4 + 1][ml] = v.y;
            Asm[kq * 4 + 2][ml] = v.z;
            Asm[kq * 4 + 3][ml] = v.w;
        }
        // stage B
#pragma unroll
        for (int i = 0; i < 4; i++) {
            int idx = tid + i * 256;
            int kl = idx >> 5;
            int nq = (idx & 31) * 4;
            *(float4*)&Bsm[kl][nq] = *(const float4*)(Bt + (size_t)(k0 + kl) * C + nq);
        }
        __syncthreads();

#pragma unroll 8
        for (int k = 0; k < BK; k++) {
            ulonglong2 av0 = *(const ulonglong2*)&Asm[k][m0];
            ulonglong2 av1 = *(const ulonglong2*)&Asm[k][m0 + 4];
            float4 b0 = *(const float4*)&Bsm[k][n0];
            float4 b1 = *(const float4*)&Bsm[k][n0 + 4];
            u64 a0 = av0.x, a1 = av0.y, a2 = av1.x, a3 = av1.y;
            u64 bb[8] = {dupf(b0.x), dupf(b0.y), dupf(b0.z), dupf(b0.w),
                         dupf(b1.x), dupf(b1.y), dupf(b1.z), dupf(b1.w)};
#pragma unroll
            for (int nn = 0; nn < 8; nn++) {
                ffma2(acc[0][nn], a0, bb[nn]);
                ffma2(acc[1][nn], a1, bb[nn]);
                ffma2(acc[2][nn], a2, bb[nn]);
                ffma2(acc[3][nn], a3, bb[nn]);
            }
        }
    }

    float4 bi0, bi1;
    if (MODE != 0) {
        bi0 = *(const float4*)(bias + n0);
        bi1 = *(const float4*)(bias + n0 + 4);
    }
#pragma unroll
    for (int mp = 0; mp < 4; mp++) {
#pragma unroll
        for (int h = 0; h < 2; h++) {
            int m = mbase + m0 + mp * 2 + h;
            if (m >= M) continue;
            float o[8];
#pragma unroll
            for (int nn = 0; nn < 8; nn++) o[nn] = h ? f2hi(acc[mp][nn]) : f2lo(acc[mp][nn]);
            if (MODE == 1) {
                int r = rowidx[m];
                const float4* xr = (const float4*)(g_xa + (size_t)r * C + n0);
                float4 x0 = xr[0], x1 = xr[1];
                o[0] += x0.x + bi0.x; o[1] += x0.y + bi0.y;
                o[2] += x0.z + bi0.z; o[3] += x0.w + bi0.w;
                o[4] += x1.x + bi1.x; o[5] += x1.y + bi1.y;
                o[6] += x1.z + bi1.z; o[7] += x1.w + bi1.w;
            } else if (MODE == 2) {
                o[0] += bi0.x; o[1] += bi0.y; o[2] += bi0.z; o[3] += bi0.w;
                o[4] += bi1.x; o[5] += bi1.y; o[6] += bi1.z; o[7] += bi1.w;
            }
            float4 w0 = {o[0], o[1], o[2], o[3]};
            float4 w1v = {o[4], o[5], o[6], o[7]};
            *(float4*)(Out + (size_t)m * C + n0) = w0;
            *(float4*)(Out + (size_t)m * C + n0 + 4) = w1v;
        }
    }
}

// ---------------- per-channel sum / sum-of-squares over an [M x 128] matrix ----------------
// SEL 0: X = g_h -> g_s1/g_q1 ; SEL 1: X = g_pre -> g_s2/g_q2
template <int SEL>
__global__ void stats_kernel(int nf4) {
    __shared__ float ss[C], qq[C];
    const float* X = SEL ? g_pre : g_h;
    float* S = SEL ? g_s2 : g_s1;
    float* Q = SEL ? g_q2 : g_q1;
    int t = threadIdx.x;
    if (t < C) { ss[t] = 0.f; qq[t] = 0.f; }
    __syncthreads();
    int g = blockIdx.x * blockDim.x + t;
    int G = gridDim.x * blockDim.x;    // multiple of 32 -> channel group fixed per thread
    float4 sv = {0.f, 0.f, 0.f, 0.f}, qv = {0.f, 0.f, 0.f, 0.f};
    for (int f = g; f < nf4; f += G) {
        float4 v = ((const float4*)X)[f];
        sv.x += v.x; qv.x += v.x * v.x;
        sv.y += v.y; qv.y += v.y * v.y;
        sv.z += v.z; qv.z += v.z * v.z;
        sv.w += v.w; qv.w += v.w * v.w;
    }
    int c = (g & 31) * 4;
    atomicAdd(&ss[c + 0], sv.x); atomicAdd(&qq[c + 0], qv.x);
    atomicAdd(&ss[c + 1], sv.y); atomicAdd(&qq[c + 1], qv.y);
    atomicAdd(&ss[c + 2], sv.z); atomicAdd(&qq[c + 2], qv.z);
    atomicAdd(&ss[c + 3], sv.w); atomicAdd(&qq[c + 3], qv.w);
    __syncthreads();
    if (t < C) { atomicAdd(&S[t], ss[t]); atomicAdd(&Q[t], qq[t]); }
}

__global__ void finalize_kernel(int sel, const float* __restrict__ bnw,
                                const float* __restrict__ bnb, float minv) {
    int j = threadIdx.x;
    float s  = sel ? g_s2[j] : g_s1[j];
    float q  = sel ? g_q2[j] : g_q1[j];
    float mu = s * minv;
    float var = q * minv - mu * mu;
    float r = rsqrtf(var + BN_EPS);
    float a = r * bnw[j];
    float c = bnb[j] - mu * a;
    if (sel) { g_a2[j] = a; g_c2[j] = c; }
    else     { g_a1[j] = a; g_c1[j] = c; }
}

// ---------------- BN1 + ELU + scatter-add into g_agg ----------------
__global__ void scatter_kernel(const int* __restrict__ col, int E) {
    int g = blockIdx.x * 256 + threadIdx.x;
    if (g >= E * 32) return;
    int e = g >> 5;
    int cq = (g & 31) * 4;
    float4 v = *(const float4*)(g_h + (size_t)g * 4);
    float4 a = *(const float4*)(g_a1 + cq);
    float4 c = *(const float4*)(g_c1 + cq);
    int d = col[e];
    float* base = g_agg + (size_t)d * C + cq;
    atomicAdd(base + 0, eluf(fmaf(v.x, a.x, c.x)));
    atomicAdd(base + 1, eluf(fmaf(v.y, a.y, c.y)));
    atomicAdd(base + 2, eluf(fmaf(v.z, a.z, c.z)));
    atomicAdd(base + 3, eluf(fmaf(v.w, a.w, c.w)));
}

// ---------------- BN2 + ELU -> output ----------------
__global__ void final_kernel(float* __restrict__ out, int n) {
    int g = blockIdx.x * 256 + threadIdx.x;
    if (g >= n * 32) return;
    int cq = (g & 31) * 4;
    float4 v = *(const float4*)(g_pre + (size_t)g * 4);
    float4 a = *(const float4*)(g_a2 + cq);
    float4 c = *(const float4*)(g_c2 + cq);
    float4 o;
    o.x = eluf(fmaf(v.x, a.x, c.x));
    o.y = eluf(fmaf(v.y, a.y, c.y));
    o.z = eluf(fmaf(v.z, a.z, c.z));
    o.w = eluf(fmaf(v.w, a.w, c.w));
    *(float4*)(out + (size_t)g * 4) = o;
}

// ---------------- launch ----------------
extern "C" void kernel_launch(void* const* d_in, const int* in_sizes, int n_in,
                              void* d_out, int out_size) {
    const float* x    = (const float*)d_in[0];
    const int*   ei   = (const int*)d_in[1];
    const float* ea   = (const float*)d_in[2];
    // d_in[3] = u (unused), d_in[4] = batch (unused)
    const float* w1   = (const float*)d_in[5];
    const float* b1   = (const float*)d_in[6];
    const float* bn1w = (const float*)d_in[7];
    const float* bn1b = (const float*)d_in[8];
    const float* w2   = (const float*)d_in[9];
    const float* b2   = (const float*)d_in[10];
    const float* bn2w = (const float*)d_in[11];
    const float* bn2b = (const float*)d_in[12];
    float* out = (float*)d_out;

    int n = in_sizes[0] / C;           // 50000
    int E = in_sizes[2] / C;           // 800000
    const int* row = ei;
    const int* col = ei + E;

    zero_kernel<<<(NN_MAX * C / 4 + 255) / 256, 256>>>();
    prep_w<<<2 * C, C>>>(w1, w2);
    count_kernel<<<(E + 255) / 256, 256>>>(col, E);
    inv_kernel<<<(n + 255) / 256, 256>>>(n);

    // xa = x @ w1a^T
    gemm_kernel<0, 128><<<(n + 127) / 128, 256>>>(x, nullptr, nullptr, n);
    // h = ea @ w1b^T + xa[row] + b1
    gemm_kernel<1, 128><<<(E + 127) / 128, 256>>>(ea, b1, row, E);

    stats_kernel<0><<<592, 256>>>(E * 32);
    finalize_kernel<<<1, C>>>(0, bn1w, bn1b, 1.f / (float)E);

    scatter_kernel<<<(E * 32 + 255) / 256, 256>>>(col, E);

    // pre = [x, agg/cnt] @ w2^T + b2
    gemm_kernel<2, 256><<<(n + 127) / 128, 256>>>(x, b2, nullptr, n);

    stats_kernel<1><<<592, 256>>>(n * 32);
    finalize_kernel<<<1, C>>>(1, bn2w, bn2b, 1.f / (float)n);

    final_kernel<<<(n * 32 + 255) / 256, 256>>>(out, n);
}